// round 11
// baseline (speedup 1.0000x reference)
#include <cuda_runtime.h>
#include <math.h>
#include <stdint.h>

// Fixed problem shapes
#define HOP 256
#define NFFT 2048
#define MH 1024
#define NPITCH 256
#define BATCH 16
#define NSAMP 480000
#define TFRAMES 1876
#define KU 103            // spectrum bins 0..102 consumed
#define KLA 102           // LA bins 0..101
#define LPAD 168          // zero-pad in front of LS (max shift 165)

struct Params {
    int   closest[NPITCH];
    int   shift[8];
    float wgt[8];
};

// Phase A/B layout padding (conflict-free for strides 1 and 64)
__device__ __forceinline__ int PHYS(int i) { return i + 4 * (i >> 6); }
// Phase B-out / C-in: element c of final-butterfly row r at 277*c + r + (r>>4)
__device__ __forceinline__ int QROW(int r) { return r + (r >> 4); }

__device__ __forceinline__ void bfly4(
    float& r0, float& i0, float& r1, float& i1,
    float& r2, float& i2, float& r3, float& i3,
    float c1, float s1, float c2, float s2, float c3, float s3)
{
    float t0r = r0 + r2, t0i = i0 + i2;
    float t1r = r1 + r3, t1i = i1 + i3;
    float t2r = r0 - r2, t2i = i0 - i2;
    float t3r = r1 - r3, t3i = i1 - i3;
    float y0r = t0r + t1r, y0i = t0i + t1i;
    float y2r = t0r - t1r, y2i = t0i - t1i;
    float y1r = t2r + t3i, y1i = t2i - t3r;
    float y3r = t2r - t3i, y3i = t2i + t3r;
    r0 = y0r;                 i0 = y0i;
    r1 = y1r * c1 - y1i * s1; i1 = y1r * s1 + y1i * c1;
    r2 = y2r * c2 - y2i * s2; i2 = y2r * s2 + y2i * c2;
    r3 = y3r * c3 - y3i * s3; i3 = y3r * s3 + y3i * c3;
}

#define CA 0.9238795325112867f
#define CB 0.3826834323650898f
#define CR 0.7071067811865476f

__global__ __launch_bounds__(64)
void pitch_kernel(const float* __restrict__ wav, float* __restrict__ out, Params p)
{
    // SH holds Z (1102 float2) during the FFT; after Phase C the front region is
    // reused for LA/CS1/LSB/RED.
    __shared__ __align__(16) float SH[2208];
    __shared__ __align__(16) float2 BND[6];   // SPX boundary values across warps

    float2* Z   = reinterpret_cast<float2*>(SH);
    float*  LA  = SH;                 // [0,104)   alias, live after Phase C
    float*  CS1 = SH + 104;           // [104,208)
    float*  LSB = SH + 208;           // [208,632)  LPAD + NPITCH
    float*  RED = SH + 632;           // [632,634)

    const int tid = threadIdx.x;     // 0..63
    const int t   = blockIdx.x;
    const int b   = blockIdx.y;
    const float* w = wav + (size_t)b * NSAMP;
    const int base = t * HOP - (NFFT / 2);

    // ================= Phase A: load + stages d4,d3 in regs ======================
    float er[16], ei[16];
    if (base >= 0 && base + NFFT <= NSAMP) {
        const float2* src = reinterpret_cast<const float2*>(w + base);
        #pragma unroll
        for (int k = 0; k < 16; ++k) {
            float2 xv = src[tid + 64 * k];
            er[k] = xv.x; ei[k] = xv.y;
        }
    } else {
        #pragma unroll
        for (int k = 0; k < 16; ++k) {
            int n  = tid + 64 * k;
            int p0 = base + 2 * n, p1 = p0 + 1;
            p0 = p0 < 0 ? -p0 : (p0 >= NSAMP ? 2 * NSAMP - 2 - p0 : p0);
            p1 = p1 < 0 ? -p1 : (p1 >= NSAMP ? 2 * NSAMP - 2 - p1 : p1);
            er[k] = w[p0]; ei[k] = w[p1];
        }
    }

    {
        float c1, s1; __sincosf((float)tid * (-6.283185307179586f / 1024.0f), &s1, &c1);
        float c2 = c1 * c1 - s1 * s1, s2 = 2.0f * c1 * s1;
        float c3 = c1 * c2 - s1 * s2, s3 = c1 * s2 + s1 * c2;
        bfly4(er[0], ei[0], er[4], ei[4], er[8], ei[8], er[12], ei[12],
              c1, s1, c2, s2, c3, s3);
        bfly4(er[1], ei[1], er[5], ei[5], er[9], ei[9], er[13], ei[13],
              c1 * CA + s1 * CB, s1 * CA - c1 * CB,
              (c2 + s2) * CR,    (s2 - c2) * CR,
              c3 * CB + s3 * CA, s3 * CB - c3 * CA);
        bfly4(er[2], ei[2], er[6], ei[6], er[10], ei[10], er[14], ei[14],
              (c1 + s1) * CR, (s1 - c1) * CR,
              s2,            -c2,
              (s3 - c3) * CR, -(c3 + s3) * CR);
        bfly4(er[3], ei[3], er[7], ei[7], er[11], ei[11], er[15], ei[15],
              c1 * CB + s1 * CA, s1 * CB - c1 * CA,
              (s2 - c2) * CR,   -(c2 + s2) * CR,
              -c3 * CA - s3 * CB, c3 * CB - s3 * CA);

        float vc1 = c2 * c2 - s2 * s2, vs1 = 2.0f * c2 * s2;
        float vc2 = vc1 * vc1 - vs1 * vs1, vs2 = 2.0f * vc1 * vs1;
        float vc3 = vc1 * vc2 - vs1 * vs2, vs3 = vc1 * vs2 + vs1 * vc2;
        #pragma unroll
        for (int b2 = 0; b2 < 4; ++b2)
            bfly4(er[4 * b2], ei[4 * b2], er[4 * b2 + 1], ei[4 * b2 + 1],
                  er[4 * b2 + 2], ei[4 * b2 + 2], er[4 * b2 + 3], ei[4 * b2 + 3],
                  vc1, vs1, vc2, vs2, vc3, vs3);
    }
    #pragma unroll
    for (int k = 0; k < 16; ++k)
        Z[PHYS(tid + 64 * k)] = make_float2(er[k], ei[k]);
    __syncthreads();

    // ================= Phase B: stages d2,d1 in regs =============================
    {
        const int H  = tid >> 2;
        const int d0 = tid & 3;
        const int h  = 4 * (H & 3) + (H >> 2);
        float fr[16], fi[16];     // index 4*d2 + d1
        #pragma unroll
        for (int d2 = 0; d2 < 4; ++d2)
            #pragma unroll
            for (int d1 = 0; d1 < 4; ++d1) {
                float2 v = Z[PHYS(64 * H + 16 * d2 + 4 * d1 + d0)];
                fr[4 * d2 + d1] = v.x; fi[4 * d2 + d1] = v.y;
            }

        // W64^d0 for d0 in {0..3}: compile-time constants, selected by d0
        float uc1 = (d0 == 0) ? 1.0f
                  : (d0 == 1) ? 0.99518472667219688624f
                  : (d0 == 2) ? 0.98078528040323044913f
                              : 0.95694033573220886494f;
        float us1 = (d0 == 0) ? 0.0f
                  : (d0 == 1) ? -0.09801714032956060199f
                  : (d0 == 2) ? -0.19509032201612826785f
                              : -0.29028467725446236764f;

        #pragma unroll
        for (int d1 = 0; d1 < 4; ++d1) {
            float bc1, bs1;
            if (d1 == 0)      { bc1 = uc1; bs1 = us1; }
            else if (d1 == 1) { bc1 = uc1 * CA + us1 * CB; bs1 = us1 * CA - uc1 * CB; }
            else if (d1 == 2) { bc1 = (uc1 + us1) * CR;    bs1 = (us1 - uc1) * CR; }
            else              { bc1 = uc1 * CB + us1 * CA; bs1 = us1 * CB - uc1 * CA; }
            float bc2 = bc1 * bc1 - bs1 * bs1, bs2 = 2.0f * bc1 * bs1;
            float bc3 = bc1 * bc2 - bs1 * bs2, bs3 = bc1 * bs2 + bs1 * bc2;
            bfly4(fr[d1], fi[d1], fr[4 + d1], fi[4 + d1],
                  fr[8 + d1], fi[8 + d1], fr[12 + d1], fi[12 + d1],
                  bc1, bs1, bc2, bs2, bc3, bs3);
        }
        {
            float q2c = uc1 * uc1 - us1 * us1, q2s = 2.0f * uc1 * us1;
            float tc1 = q2c * q2c - q2s * q2s, ts1 = 2.0f * q2c * q2s;
            float tc2 = tc1 * tc1 - ts1 * ts1, ts2 = 2.0f * tc1 * ts1;
            float tc3 = tc1 * tc2 - ts1 * ts2, ts3 = tc1 * ts2 + ts1 * tc2;
            #pragma unroll
            for (int d2 = 0; d2 < 4; ++d2)
                bfly4(fr[4 * d2], fi[4 * d2], fr[4 * d2 + 1], fi[4 * d2 + 1],
                      fr[4 * d2 + 2], fi[4 * d2 + 2], fr[4 * d2 + 3], fi[4 * d2 + 3],
                      tc1, ts1, tc2, ts2, tc3, ts3);
        }

        __syncthreads();    // all PHYS reads complete before relayout rewrite

        // writeback bin-indexed: final bin row of butterfly B=16H+4d2+d1 is
        // r = 16W + h with W = 4*d1 + d2. Element c=d0 at 277*d0 + 17W + h.
        // Liveness (r<=102 or r>=154): W 7,8 dead; W6 needs h<=6; W9 needs h>=10.
        #pragma unroll
        for (int d2 = 0; d2 < 4; ++d2)
            #pragma unroll
            for (int d1 = 0; d1 < 4; ++d1) {
                const int W = 4 * d1 + d2;
                if (W == 7 || W == 8) continue;
                bool store = true;
                if (W == 6) store = (h <= 6);
                if (W == 9) store = (h >= 10);
                if (store)
                    Z[277 * d0 + 17 * W + h] =
                        make_float2(fr[4 * d2 + d1], fi[4 * d2 + d1]);
            }
    }
    __syncthreads();

    // ========== Phase C: final stage + rfft unpack -> registers X0, X1 ===========
    float2 X0, X1 = make_float2(0.f, 0.f);
    {
        #pragma unroll
        for (int it = 0; it < 2; ++it) {
            int k = tid + 64 * it;
            if (it == 0 || k < KU) {
                int ra = QROW(k);
                float2 a0 = Z[ra];
                float2 a1 = Z[ra + 277];
                float2 a2 = Z[ra + 554];
                float2 a3 = Z[ra + 831];
                float Ar = (a0.x + a2.x) + (a1.x + a3.x);
                float Ai = (a0.y + a2.y) + (a1.y + a3.y);
                float Br, Bi;
                if (k == 0) { Br = Ar; Bi = Ai; }
                else {
                    int rb = QROW(256 - k);
                    float2 b0 = Z[rb];
                    float2 b1 = Z[rb + 277];
                    float2 b2 = Z[rb + 554];
                    float2 b3 = Z[rb + 831];
                    float t2r = b0.x - b2.x, t2i = b0.y - b2.y;
                    float t3r = b1.x - b3.x, t3i = b1.y - b3.y;
                    Br = t2r - t3i; Bi = t2i + t3r;       // y3 -> bin 1024-k
                }
                float zer =  0.5f * (Ar + Br);
                float zei =  0.5f * (Ai - Bi);
                float zor =  0.5f * (Ai + Bi);
                float zoi = -0.5f * (Ar - Br);
                float sn, cs;
                __sincosf((float)k * (-3.141592653589793f / 1024.0f), &sn, &cs);
                float2 Xv = make_float2(zer + cs * zor - sn * zoi,
                                        zei + cs * zoi + sn * zor);
                if (it == 0) X0 = Xv; else X1 = Xv;
            }
        }
        // boundary values needed across warp edges for the window conv
        if (tid == 31) { BND[0] = X0; BND[4] = X1; }   // SPX31, SPX95
        if (tid == 32) { BND[1] = X0; BND[5] = X1; }   // SPX32, SPX96
        if (tid == 63) { BND[2] = X0; }                // SPX63
        if (tid == 0)  { BND[3] = X1; }                // SPX64
    }
    __syncthreads();   // Z reads complete (alias region now writable); BND visible

    // ====== fused window conv: Xw = 0.5 X[k] - 0.25(X[k-1]+X[k+1]); LA = log|Xw|
    {
        const unsigned FM = 0xffffffffu;
        const int lane = tid & 31;
        float2 X0p, X0m, X1p, X1m;
        X0p.x = __shfl_down_sync(FM, X0.x, 1);
        X0p.y = __shfl_down_sync(FM, X0.y, 1);
        X0m.x = __shfl_up_sync(FM, X0.x, 1);
        X0m.y = __shfl_up_sync(FM, X0.y, 1);
        X1p.x = __shfl_down_sync(FM, X1.x, 1);
        X1p.y = __shfl_down_sync(FM, X1.y, 1);
        X1m.x = __shfl_up_sync(FM, X1.x, 1);
        X1m.y = __shfl_up_sync(FM, X1.y, 1);
        if (lane == 31) X0p = (tid == 31) ? BND[1] : BND[3];   // SPX32 / SPX64
        if (lane == 31) X1p = BND[5];                          // SPX96 (tid 31 only used)
        if (tid == 32)  X0m = BND[0];                          // SPX31
        if (tid == 0)   X0m = make_float2(X0p.x, -X0p.y);      // conj(SPX1)
        if (tid == 0)   X1m = BND[2];                          // SPX63
        if (tid == 32)  X1m = BND[4];                          // SPX95

        {
            float xr = 0.5f * X0.x - 0.25f * (X0m.x + X0p.x);
            float xi = 0.5f * X0.y - 0.25f * (X0m.y + X0p.y);
            LA[tid] = __logf(sqrtf(xr * xr + xi * xi) + 1e-8f);
        }
        if (tid < 38) {
            float xr = 0.5f * X1.x - 0.25f * (X1m.x + X1p.x);
            float xi = 0.5f * X1.y - 0.25f * (X1m.y + X1p.y);
            LA[tid + 64] = __logf(sqrtf(xr * xr + xi * xi) + 1e-8f);
        }
        if (tid < 2) LA[KLA + tid] = 0.f;
        // zero LS front padding (aliased over dead Z; consumed after next barriers)
        if (tid < LPAD / 4)
            reinterpret_cast<float4*>(LSB)[tid] = make_float4(0.f, 0.f, 0.f, 0.f);
    }
    __syncthreads();

    // ================= single-pass scan (warp 0): CS1 inclusive ==================
    if (tid < 32) {
        float v0 = 0.f, v1 = 0.f, v2 = 0.f, v3 = 0.f;
        if (tid < 26) {
            float4 q = reinterpret_cast<const float4*>(LA)[tid];
            v0 = q.x; v1 = q.y; v2 = q.z; v3 = q.w;
        }
        float p1 = v0 + v1, p2 = p1 + v2, p3 = p2 + v3;
        float s = p3;
        #pragma unroll
        for (int o = 1; o < 32; o <<= 1) {
            float u = __shfl_up_sync(0xffffffffu, s, o);
            if (tid >= o) s += u;
        }
        float excl = s - p3;
        if (tid < 26)
            reinterpret_cast<float4*>(CS1)[tid] =
                make_float4(excl + v0, excl + p1, excl + p2, excl + p3);
    }
    __syncthreads();

    // ============ fine structure: 4 consecutive pitch bins per thread ============
    float lsv[4];
    {
        int4 c4 = reinterpret_cast<const int4*>(p.closest)[tid];
        int cis[4] = {c4.x, c4.y, c4.z, c4.w};
        float LA0 = LA[0];
        #pragma unroll
        for (int j = 0; j < 4; ++j) {
            int ci = cis[j];                  // 3..85
            int lo = ci - 15, hi = ci + 16;   // hi <= 101
            float sum = (lo <= 0) ? fmaf((float)(-lo), LA0, CS1[hi])
                                  : CS1[hi] - CS1[lo - 1];
            lsv[j] = __expf(LA[ci] - sum * 0.03125f);
        }
        *reinterpret_cast<float4*>(&LSB[LPAD + 4 * tid]) =
            make_float4(lsv[0], lsv[1], lsv[2], lsv[3]);
    }
    __syncthreads();

    // ================= subharmonic summation (zero-padded, guard-free) ==========
    float acc[4] = {lsv[0], lsv[1], lsv[2], lsv[3]};
    #pragma unroll
    for (int n = 1; n < 8; ++n) {
        int   sh = p.shift[n];
        float wn = p.wgt[n];
        int   bi = LPAD + 4 * tid - sh;       // >= 3 always
        if ((sh & 3) == 0) {
            float4 q = *reinterpret_cast<const float4*>(&LSB[bi]);
            acc[0] = fmaf(wn, q.x, acc[0]);
            acc[1] = fmaf(wn, q.y, acc[1]);
            acc[2] = fmaf(wn, q.z, acc[2]);
            acc[3] = fmaf(wn, q.w, acc[3]);
        } else if ((sh & 1) == 0) {
            float2 qa = *reinterpret_cast<const float2*>(&LSB[bi]);
            float2 qb = *reinterpret_cast<const float2*>(&LSB[bi + 2]);
            acc[0] = fmaf(wn, qa.x, acc[0]);
            acc[1] = fmaf(wn, qa.y, acc[1]);
            acc[2] = fmaf(wn, qb.x, acc[2]);
            acc[3] = fmaf(wn, qb.y, acc[3]);
        } else {
            #pragma unroll
            for (int j = 0; j < 4; ++j)
                acc[j] = fmaf(wn, LSB[bi + j], acc[j]);
        }
    }

    // ================= per-frame max, normalize, store ===========================
    float mloc = fmaxf(fmaxf(acc[0], acc[1]), fmaxf(acc[2], acc[3]));
    #pragma unroll
    for (int o = 16; o; o >>= 1)
        mloc = fmaxf(mloc, __shfl_xor_sync(0xffffffffu, mloc, o));
    if ((tid & 31) == 0) RED[tid >> 5] = mloc;
    __syncthreads();
    float mx = fmaxf(fmaxf(RED[0], RED[1]), 1e-8f);

    float4 o4;
    o4.x = __fdividef(acc[0], mx);
    o4.y = __fdividef(acc[1], mx);
    o4.z = __fdividef(acc[2], mx);
    o4.w = __fdividef(acc[3], mx);
    reinterpret_cast<float4*>(out + ((size_t)b * TFRAMES + t) * NPITCH)[tid] = o4;
}

extern "C" void kernel_launch(void* const* d_in, const int* in_sizes, int n_in,
                              void* d_out, int out_size)
{
    (void)in_sizes; (void)n_in; (void)out_size;
    const float* wav = (const float*)d_in[0];
    float* out = (float*)d_out;

    Params p;

    // Gather indices: f32 argmin over |linspace(0,12000,1025) - center_freq|
    const double l40 = log(40.0), l1000 = log(1000.0);
    for (int j = 0; j < NPITCH; ++j) {
        double cd = exp(l40 + (double)j * (l1000 - l40) / 255.0);
        float  cf = (float)cd;
        const float step = 11.71875f;
        int i0 = (int)(cd / 11.71875);
        int best = 0; float bestd = 3.4e38f;
        for (int i = i0 - 2; i <= i0 + 2; ++i) {
            int ic = i < 0 ? 0 : (i > 1024 ? 1024 : i);
            float d = fabsf((float)ic * step - cf);
            if (d < bestd) { bestd = d; best = ic; }
        }
        p.closest[j] = best;
    }

    // Harmonic shifts: Python round() == rint (half-even), identical expression
    const double cpb = 1200.0 * log2(25.0) / 255.0;
    p.shift[0] = 0; p.wgt[0] = 1.0f;
    for (int n = 2; n <= 8; ++n) {
        p.shift[n - 1] = (int)rint(1200.0 * log2((double)n) / cpb);
        p.wgt[n - 1]   = (float)pow(0.86, (double)(n - 1));
    }

    dim3 grid(TFRAMES, BATCH);
    pitch_kernel<<<grid, 64>>>(wav, out, p);
}

// round 12
// speedup vs baseline: 1.0565x; 1.0565x over previous
#include <cuda_runtime.h>
#include <math.h>
#include <stdint.h>

// Fixed problem shapes
#define HOP 256
#define NFFT 2048
#define NPITCH 256
#define BATCH 16
#define NSAMP 480000
#define TFRAMES 1876
#define KLA 102           // LA bins 0..101
#define LPAD 168          // zero-pad in front of LS (max shift 165)

struct Params {
    int   closest[NPITCH];
    int   shift[8];
    float wgt[8];
};

#define CR 0.7071067811865476f

__device__ __forceinline__ void bfly4(
    float& r0, float& i0, float& r1, float& i1,
    float& r2, float& i2, float& r3, float& i3,
    float c1, float s1, float c2, float s2, float c3, float s3)
{
    float t0r = r0 + r2, t0i = i0 + i2;
    float t1r = r1 + r3, t1i = i1 + i3;
    float t2r = r0 - r2, t2i = i0 - i2;
    float t3r = r1 - r3, t3i = i1 - i3;
    float y0r = t0r + t1r, y0i = t0i + t1i;
    float y2r = t0r - t1r, y2i = t0i - t1i;
    float y1r = t2r + t3i, y1i = t2i - t3r;
    float y3r = t2r - t3i, y3i = t2i + t3r;
    r0 = y0r;                 i0 = y0i;
    r1 = y1r * c1 - y1i * s1; i1 = y1r * s1 + y1i * c1;
    r2 = y2r * c2 - y2i * s2; i2 = y2r * s2 + y2i * c2;
    r3 = y3r * c3 - y3i * s3; i3 = y3r * s3 + y3i * c3;
}

// In-register 32-pt DIF FFT (radix 4,4,2). Output position p holds bin
// k = (p>>3) + 4*((p>>1)&3) + 16*(p&1). All twiddles are literals.
__device__ __forceinline__ void fft32(float* zr, float* zi)
{
    constexpr float T32C[8] = { 1.0f, 0.98078528040323044913f, 0.92387953251128675613f,
        0.83146961230254523708f, 0.70710678118654752440f, 0.55557023301960222474f,
        0.38268343236508977173f, 0.19509032201612826785f };
    constexpr float T32S[8] = { 0.0f, -0.19509032201612826785f, -0.38268343236508977173f,
        -0.55557023301960222474f, -0.70710678118654752440f, -0.83146961230254523708f,
        -0.92387953251128675613f, -0.98078528040323044913f };
    constexpr float T16C[8] = { 1.0f, 0.92387953251128675613f, 0.70710678118654752440f,
        0.38268343236508977173f, 0.0f, -0.38268343236508977173f,
        -0.70710678118654752440f, -0.92387953251128675613f };
    constexpr float T16S[8] = { 0.0f, -0.38268343236508977173f, -0.70710678118654752440f,
        -0.92387953251128675613f, -1.0f, -0.92387953251128675613f,
        -0.70710678118654752440f, -0.38268343236508977173f };
    constexpr float T96C[8] = { 1.0f, 0.83146961230254523708f, 0.38268343236508977173f,
        -0.19509032201612826785f, -0.70710678118654752440f, -0.98078528040323044913f,
        -0.92387953251128675613f, -0.55557023301960222474f };
    constexpr float T96S[8] = { 0.0f, -0.55557023301960222474f, -0.92387953251128675613f,
        -0.98078528040323044913f, -0.70710678118654752440f, -0.19509032201612826785f,
        0.38268343236508977173f, 0.83146961230254523708f };

    // stage 1: L=32 (Q=8), twiddles W32^q, W32^2q, W32^3q
    #pragma unroll
    for (int q = 0; q < 8; ++q)
        bfly4(zr[q], zi[q], zr[q + 8], zi[q + 8], zr[q + 16], zi[q + 16],
              zr[q + 24], zi[q + 24],
              T32C[q], T32S[q], T16C[q], T16S[q], T96C[q], T96S[q]);

    // stage 2: L=8 (Q=2) within each block of 8
    #pragma unroll
    for (int g = 0; g < 4; ++g) {
        const int bb = 8 * g;
        bfly4(zr[bb], zi[bb], zr[bb + 2], zi[bb + 2], zr[bb + 4], zi[bb + 4],
              zr[bb + 6], zi[bb + 6], 1.f, 0.f, 1.f, 0.f, 1.f, 0.f);
        bfly4(zr[bb + 1], zi[bb + 1], zr[bb + 3], zi[bb + 3], zr[bb + 5], zi[bb + 5],
              zr[bb + 7], zi[bb + 7], CR, -CR, 0.f, -1.f, -CR, -CR);
    }

    // stage 3: radix-2 pairs, no twiddle
    #pragma unroll
    for (int m = 0; m < 16; ++m) {
        float ar = zr[2 * m], ai = zi[2 * m];
        float br = zr[2 * m + 1], bi = zi[2 * m + 1];
        zr[2 * m] = ar + br;     zi[2 * m] = ai + bi;
        zr[2 * m + 1] = ar - br; zi[2 * m + 1] = ai - bi;
    }
}

__global__ __launch_bounds__(32)
void pitch_kernel(const float* __restrict__ wav, float* __restrict__ out, Params p)
{
    // TR (transpose buffer, 33-padded 32x32 float2) then SA/SB (needed FFT bins).
    // After the transpose region is dead, SPX/LA/CS1/LSB alias over it.
    __shared__ __align__(16) float SH[2528];
    float2* TR  = reinterpret_cast<float2*>(SH);            // [0,1056) f2
    float2* SA  = reinterpret_cast<float2*>(SH + 2112);     // bins 0..102
    float2* SB  = reinterpret_cast<float2*>(SH + 2318);     // bins 922..1023 (SB[m]=922+m)
    float2* SPX = reinterpret_cast<float2*>(SH);            // alias: unpacked bins 0..102
    float*  LA  = SH + 208;                                 // [208,312)
    float*  CS1 = SH + 312;                                 // [312,416)
    float*  LSB = SH + 416;                                 // [416,840)

    const int lane = threadIdx.x;     // 0..31
    const int t    = blockIdx.x;
    const int b    = blockIdx.y;
    const float* w = wav + (size_t)b * NSAMP;
    const int base = t * HOP - (NFFT / 2);

    // ---- load: thread n2=lane holds packed z[32*n1 + lane], n1 = 0..31 ----
    float zr[32], zi[32];
    if (base >= 0 && base + NFFT <= NSAMP) {
        const float2* src = reinterpret_cast<const float2*>(w + base);
        #pragma unroll
        for (int n1 = 0; n1 < 32; ++n1) {
            float2 v = src[32 * n1 + lane];
            zr[n1] = v.x; zi[n1] = v.y;
        }
    } else {
        #pragma unroll
        for (int n1 = 0; n1 < 32; ++n1) {
            int m  = 32 * n1 + lane;
            int p0 = base + 2 * m, p1 = p0 + 1;
            p0 = p0 < 0 ? -p0 : (p0 >= NSAMP ? 2 * NSAMP - 2 - p0 : p0);
            p1 = p1 < 0 ? -p1 : (p1 >= NSAMP ? 2 * NSAMP - 2 - p1 : p1);
            zr[n1] = w[p0]; zi[n1] = w[p1];
        }
    }

    // ---- step 1: 32-pt FFT over n1 ----
    fft32(zr, zi);

    // ---- twiddle W1024^{n2*k1} and transpose-store (row k1, col n2) ----
    {
        float bs, bc; __sincosf((float)lane * (-6.283185307179586f / 1024.0f), &bs, &bc);
        float b2c = bc * bc - bs * bs, b2s = 2.0f * bc * bs;
        float b3c = bc * b2c - bs * b2s, b3s = bc * b2s + bs * b2c;
        float b4c = b2c * b2c - b2s * b2s, b4s = 2.0f * b2c * b2s;
        float wc = 1.0f, ws = 0.0f;            // W^(4*j32)
        #pragma unroll
        for (int j32 = 0; j32 < 8; ++j32) {
            #pragma unroll
            for (int j = 0; j < 4; ++j) {
                const int k1 = 4 * j32 + j;
                const int pp = 8 * (k1 & 3) + 2 * ((k1 >> 2) & 3) + (k1 >> 4);
                float twc, tws;
                if (j == 0)      { twc = wc; tws = ws; }
                else if (j == 1) { twc = wc * bc - ws * bs;   tws = wc * bs + ws * bc; }
                else if (j == 2) { twc = wc * b2c - ws * b2s; tws = wc * b2s + ws * b2c; }
                else             { twc = wc * b3c - ws * b3s; tws = wc * b3s + ws * b3c; }
                TR[33 * k1 + lane] = make_float2(zr[pp] * twc - zi[pp] * tws,
                                                 zr[pp] * tws + zi[pp] * twc);
            }
            float nc = wc * b4c - ws * b4s, ns = wc * b4s + ws * b4c;
            wc = nc; ws = ns;
        }
    }
    __syncwarp();

    // ---- transpose-load (thread becomes k1=lane) + step 2: 32-pt FFT over n2 ----
    #pragma unroll
    for (int n2 = 0; n2 < 32; ++n2) {
        float2 v = TR[33 * lane + n2];
        zr[n2] = v.x; zi[n2] = v.y;
    }
    fft32(zr, zi);

    // ---- extract needed bins k = k1 + 32*k2 (k<=102 or k>=922) ----
    // positions: k2=0,1,2,3 -> p=0,8,16,24 ; k2=28,29,30,31 -> p=7,15,23,31
    SA[lane]      = make_float2(zr[0],  zi[0]);     // bin lane
    SA[lane + 32] = make_float2(zr[8],  zi[8]);     // bin lane+32
    SA[lane + 64] = make_float2(zr[16], zi[16]);    // bin lane+64
    if (lane <= 6)  SA[lane + 96] = make_float2(zr[24], zi[24]);   // bin lane+96
    if (lane >= 26) SB[lane - 26] = make_float2(zr[7],  zi[7]);    // bin lane+896
    SB[lane + 6]  = make_float2(zr[15], zi[15]);    // bin lane+928
    SB[lane + 38] = make_float2(zr[23], zi[23]);    // bin lane+960
    SB[lane + 70] = make_float2(zr[31], zi[31]);    // bin lane+992
    __syncwarp();

    // ---- rfft unpack -> SPX[0..102] (aliases dead TR region) ----
    #pragma unroll
    for (int it = 0; it < 4; ++it) {
        int k = lane + 32 * it;
        if (it < 3 || lane <= 6) {
            float2 A  = SA[k];
            float2 Bv = (k == 0) ? A : SB[102 - k];     // bin 1024-k = 922+(102-k)
            float zer =  0.5f * (A.x + Bv.x);
            float zei =  0.5f * (A.y - Bv.y);
            float zor =  0.5f * (A.y + Bv.y);
            float zoi = -0.5f * (A.x - Bv.x);
            float sn, cs;
            __sincosf((float)k * (-3.141592653589793f / 1024.0f), &sn, &cs);
            SPX[k] = make_float2(zer + cs * zor - sn * zoi,
                                 zei + cs * zoi + sn * zor);
        }
    }
    __syncwarp();

    // ---- window as spectral conv + log magnitude -> LA[0..101] ----
    #pragma unroll
    for (int it = 0; it < 4; ++it) {
        int k = lane + 32 * it;
        if (it < 3 || lane <= 5) {      // k < 102
            float2 Xc = SPX[k];
            float2 Xp = SPX[k + 1];
            float2 Xm = (k == 0) ? make_float2(SPX[1].x, -SPX[1].y) : SPX[k - 1];
            float xr = 0.5f * Xc.x - 0.25f * (Xm.x + Xp.x);
            float xi = 0.5f * Xc.y - 0.25f * (Xm.y + Xp.y);
            LA[k] = __logf(sqrtf(xr * xr + xi * xi) + 1e-8f);
        }
    }
    if (lane < 2) LA[KLA + lane] = 0.f;
    // zero LS front padding (42 float4)
    #pragma unroll
    for (int i = lane; i < LPAD / 4; i += 32)
        reinterpret_cast<float4*>(LSB)[i] = make_float4(0.f, 0.f, 0.f, 0.f);
    __syncwarp();

    // ---- single-pass warp scan: CS1 inclusive prefix of LA ----
    {
        float v0 = 0.f, v1 = 0.f, v2 = 0.f, v3 = 0.f;
        if (lane < 26) {
            float4 q = reinterpret_cast<const float4*>(LA)[lane];
            v0 = q.x; v1 = q.y; v2 = q.z; v3 = q.w;
        }
        float p1 = v0 + v1, p2 = p1 + v2, p3 = p2 + v3;
        float s = p3;
        #pragma unroll
        for (int o = 1; o < 32; o <<= 1) {
            float u = __shfl_up_sync(0xffffffffu, s, o);
            if (lane >= o) s += u;
        }
        float excl = s - p3;
        if (lane < 26)
            reinterpret_cast<float4*>(CS1)[lane] =
                make_float4(excl + v0, excl + p1, excl + p2, excl + p3);
    }
    __syncwarp();

    // ---- fine structure: 8 pitch bins per thread (two float4 groups) ----
    float lsv[2][4];
    #pragma unroll
    for (int g = 0; g < 2; ++g) {
        int vt = lane + 32 * g;
        int4 c4 = reinterpret_cast<const int4*>(p.closest)[vt];
        int cis[4] = {c4.x, c4.y, c4.z, c4.w};
        float LA0 = LA[0];
        #pragma unroll
        for (int j = 0; j < 4; ++j) {
            int ci = cis[j];                  // 3..85
            int lo = ci - 15, hi = ci + 16;   // hi <= 101
            float sum = (lo <= 0) ? fmaf((float)(-lo), LA0, CS1[hi])
                                  : CS1[hi] - CS1[lo - 1];
            lsv[g][j] = __expf(LA[ci] - sum * 0.03125f);
        }
        *reinterpret_cast<float4*>(&LSB[LPAD + 4 * vt]) =
            make_float4(lsv[g][0], lsv[g][1], lsv[g][2], lsv[g][3]);
    }
    __syncwarp();

    // ---- subharmonic summation (zero-padded, guard-free) ----
    float acc[2][4];
    #pragma unroll
    for (int g = 0; g < 2; ++g)
        #pragma unroll
        for (int j = 0; j < 4; ++j) acc[g][j] = lsv[g][j];

    #pragma unroll
    for (int n = 1; n < 8; ++n) {
        int   sh = p.shift[n];
        float wn = p.wgt[n];
        #pragma unroll
        for (int g = 0; g < 2; ++g) {
            int bi = LPAD + 4 * (lane + 32 * g) - sh;     // >= 3 always
            if ((sh & 3) == 0) {
                float4 q = *reinterpret_cast<const float4*>(&LSB[bi]);
                acc[g][0] = fmaf(wn, q.x, acc[g][0]);
                acc[g][1] = fmaf(wn, q.y, acc[g][1]);
                acc[g][2] = fmaf(wn, q.z, acc[g][2]);
                acc[g][3] = fmaf(wn, q.w, acc[g][3]);
            } else if ((sh & 1) == 0) {
                float2 qa = *reinterpret_cast<const float2*>(&LSB[bi]);
                float2 qb = *reinterpret_cast<const float2*>(&LSB[bi + 2]);
                acc[g][0] = fmaf(wn, qa.x, acc[g][0]);
                acc[g][1] = fmaf(wn, qa.y, acc[g][1]);
                acc[g][2] = fmaf(wn, qb.x, acc[g][2]);
                acc[g][3] = fmaf(wn, qb.y, acc[g][3]);
            } else {
                #pragma unroll
                for (int j = 0; j < 4; ++j)
                    acc[g][j] = fmaf(wn, LSB[bi + j], acc[g][j]);
            }
        }
    }

    // ---- per-frame max (pure warp shuffle), normalize, store ----
    float mloc = -3.4e38f;
    #pragma unroll
    for (int g = 0; g < 2; ++g)
        #pragma unroll
        for (int j = 0; j < 4; ++j) mloc = fmaxf(mloc, acc[g][j]);
    #pragma unroll
    for (int o = 16; o; o >>= 1)
        mloc = fmaxf(mloc, __shfl_xor_sync(0xffffffffu, mloc, o));
    float mx = fmaxf(mloc, 1e-8f);

    float4* optr = reinterpret_cast<float4*>(out + ((size_t)b * TFRAMES + t) * NPITCH);
    #pragma unroll
    for (int g = 0; g < 2; ++g) {
        float4 o4;
        o4.x = __fdividef(acc[g][0], mx);
        o4.y = __fdividef(acc[g][1], mx);
        o4.z = __fdividef(acc[g][2], mx);
        o4.w = __fdividef(acc[g][3], mx);
        optr[lane + 32 * g] = o4;
    }
}

extern "C" void kernel_launch(void* const* d_in, const int* in_sizes, int n_in,
                              void* d_out, int out_size)
{
    (void)in_sizes; (void)n_in; (void)out_size;
    const float* wav = (const float*)d_in[0];
    float* out = (float*)d_out;

    Params p;

    // Gather indices: f32 argmin over |linspace(0,12000,1025) - center_freq|
    const double l40 = log(40.0), l1000 = log(1000.0);
    for (int j = 0; j < NPITCH; ++j) {
        double cd = exp(l40 + (double)j * (l1000 - l40) / 255.0);
        float  cf = (float)cd;
        const float step = 11.71875f;
        int i0 = (int)(cd / 11.71875);
        int best = 0; float bestd = 3.4e38f;
        for (int i = i0 - 2; i <= i0 + 2; ++i) {
            int ic = i < 0 ? 0 : (i > 1024 ? 1024 : i);
            float d = fabsf((float)ic * step - cf);
            if (d < bestd) { bestd = d; best = ic; }
        }
        p.closest[j] = best;
    }

    // Harmonic shifts: Python round() == rint (half-even), identical expression
    const double cpb = 1200.0 * log2(25.0) / 255.0;
    p.shift[0] = 0; p.wgt[0] = 1.0f;
    for (int n = 2; n <= 8; ++n) {
        p.shift[n - 1] = (int)rint(1200.0 * log2((double)n) / cpb);
        p.wgt[n - 1]   = (float)pow(0.86, (double)(n - 1));
    }

    dim3 grid(TFRAMES, BATCH);
    pitch_kernel<<<grid, 32>>>(wav, out, p);
}

// round 13
// speedup vs baseline: 1.0826x; 1.0247x over previous
#include <cuda_runtime.h>
#include <math.h>
#include <stdint.h>

// Fixed problem shapes
#define HOP 256
#define NFFT 2048
#define NPITCH 256
#define BATCH 16
#define NSAMP 480000
#define TFRAMES 1876
#define KLA 102           // LA bins 0..101
#define LPAD 168          // zero-pad in front of LS (max shift 165)

struct Params {
    int   closest[NPITCH];
    int   shift[8];
    float wgt[8];
};

#define CR 0.7071067811865476f

__device__ __forceinline__ void bfly4(
    float& r0, float& i0, float& r1, float& i1,
    float& r2, float& i2, float& r3, float& i3,
    float c1, float s1, float c2, float s2, float c3, float s3)
{
    float t0r = r0 + r2, t0i = i0 + i2;
    float t1r = r1 + r3, t1i = i1 + i3;
    float t2r = r0 - r2, t2i = i0 - i2;
    float t3r = r1 - r3, t3i = i1 - i3;
    float y0r = t0r + t1r, y0i = t0i + t1i;
    float y2r = t0r - t1r, y2i = t0i - t1i;
    float y1r = t2r + t3i, y1i = t2i - t3r;
    float y3r = t2r - t3i, y3i = t2i + t3r;
    r0 = y0r;                 i0 = y0i;
    r1 = y1r * c1 - y1i * s1; i1 = y1r * s1 + y1i * c1;
    r2 = y2r * c2 - y2i * s2; i2 = y2r * s2 + y2i * c2;
    r3 = y3r * c3 - y3i * s3; i3 = y3r * s3 + y3i * c3;
}

// In-register 32-pt DIF FFT (radix 4,4,2). Output position p holds bin
// k = (p>>3) + 4*((p>>1)&3) + 16*(p&1). All twiddles are literals.
__device__ __forceinline__ void fft32(float* zr, float* zi)
{
    constexpr float T32C[8] = { 1.0f, 0.98078528040323044913f, 0.92387953251128675613f,
        0.83146961230254523708f, 0.70710678118654752440f, 0.55557023301960222474f,
        0.38268343236508977173f, 0.19509032201612826785f };
    constexpr float T32S[8] = { 0.0f, -0.19509032201612826785f, -0.38268343236508977173f,
        -0.55557023301960222474f, -0.70710678118654752440f, -0.83146961230254523708f,
        -0.92387953251128675613f, -0.98078528040323044913f };
    constexpr float T16C[8] = { 1.0f, 0.92387953251128675613f, 0.70710678118654752440f,
        0.38268343236508977173f, 0.0f, -0.38268343236508977173f,
        -0.70710678118654752440f, -0.92387953251128675613f };
    constexpr float T16S[8] = { 0.0f, -0.38268343236508977173f, -0.70710678118654752440f,
        -0.92387953251128675613f, -1.0f, -0.92387953251128675613f,
        -0.70710678118654752440f, -0.38268343236508977173f };
    constexpr float T96C[8] = { 1.0f, 0.83146961230254523708f, 0.38268343236508977173f,
        -0.19509032201612826785f, -0.70710678118654752440f, -0.98078528040323044913f,
        -0.92387953251128675613f, -0.55557023301960222474f };
    constexpr float T96S[8] = { 0.0f, -0.55557023301960222474f, -0.92387953251128675613f,
        -0.98078528040323044913f, -0.70710678118654752440f, -0.19509032201612826785f,
        0.38268343236508977173f, 0.83146961230254523708f };

    #pragma unroll
    for (int q = 0; q < 8; ++q)
        bfly4(zr[q], zi[q], zr[q + 8], zi[q + 8], zr[q + 16], zi[q + 16],
              zr[q + 24], zi[q + 24],
              T32C[q], T32S[q], T16C[q], T16S[q], T96C[q], T96S[q]);

    #pragma unroll
    for (int g = 0; g < 4; ++g) {
        const int bb = 8 * g;
        bfly4(zr[bb], zi[bb], zr[bb + 2], zi[bb + 2], zr[bb + 4], zi[bb + 4],
              zr[bb + 6], zi[bb + 6], 1.f, 0.f, 1.f, 0.f, 1.f, 0.f);
        bfly4(zr[bb + 1], zi[bb + 1], zr[bb + 3], zi[bb + 3], zr[bb + 5], zi[bb + 5],
              zr[bb + 7], zi[bb + 7], CR, -CR, 0.f, -1.f, -CR, -CR);
    }

    #pragma unroll
    for (int m = 0; m < 16; ++m) {
        float ar = zr[2 * m], ai = zi[2 * m];
        float br = zr[2 * m + 1], bi = zi[2 * m + 1];
        zr[2 * m] = ar + br;     zi[2 * m] = ai + bi;
        zr[2 * m + 1] = ar - br; zi[2 * m + 1] = ai - bi;
    }
}

__global__ __launch_bounds__(32)
void pitch_kernel(const float* __restrict__ wav, float* __restrict__ out, Params p)
{
    // TR: XOR-swizzled 32x32 float2 transpose buffer (exactly 1024 f2 = 8192 B).
    // After TR is consumed, SPX/LA/CS1/LSB alias the same storage.
    __shared__ __align__(16) float SH[2048];
    float2* TR  = reinterpret_cast<float2*>(SH);
    float2* SPX = reinterpret_cast<float2*>(SH);            // bins 0..102 (f2[0..103))
    float*  LA  = SH + 208;                                 // [208,312)
    float*  CS1 = SH + 312;                                 // [312,416)
    float*  LSB = SH + 416;                                 // [416,840)

    const int lane = threadIdx.x;     // 0..31
    const int t    = blockIdx.x;
    const int b    = blockIdx.y;
    const float* w = wav + (size_t)b * NSAMP;
    const int base = t * HOP - (NFFT / 2);
    const unsigned FM = 0xffffffffu;

    // ---- load: thread n2=lane holds packed z[32*n1 + lane], n1 = 0..31 ----
    float zr[32], zi[32];
    if (base >= 0 && base + NFFT <= NSAMP) {
        const float2* src = reinterpret_cast<const float2*>(w + base);
        #pragma unroll
        for (int n1 = 0; n1 < 32; ++n1) {
            float2 v = src[32 * n1 + lane];
            zr[n1] = v.x; zi[n1] = v.y;
        }
    } else {
        #pragma unroll
        for (int n1 = 0; n1 < 32; ++n1) {
            int m  = 32 * n1 + lane;
            int p0 = base + 2 * m, p1 = p0 + 1;
            p0 = p0 < 0 ? -p0 : (p0 >= NSAMP ? 2 * NSAMP - 2 - p0 : p0);
            p1 = p1 < 0 ? -p1 : (p1 >= NSAMP ? 2 * NSAMP - 2 - p1 : p1);
            zr[n1] = w[p0]; zi[n1] = w[p1];
        }
    }

    // ---- step 1: full 32-pt FFT over n1 ----
    fft32(zr, zi);

    // ---- twiddle W1024^{n2*k1} and transpose-store (row k1, XOR swizzle) ----
    {
        float bs, bc; __sincosf((float)lane * (-6.283185307179586f / 1024.0f), &bs, &bc);
        float b2c = bc * bc - bs * bs, b2s = 2.0f * bc * bs;
        float b3c = bc * b2c - bs * b2s, b3s = bc * b2s + bs * b2c;
        float b4c = b2c * b2c - b2s * b2s, b4s = 2.0f * b2c * b2s;
        float wc = 1.0f, ws = 0.0f;            // W^(4*j32*lane)
        #pragma unroll
        for (int j32 = 0; j32 < 8; ++j32) {
            #pragma unroll
            for (int j = 0; j < 4; ++j) {
                const int k1 = 4 * j32 + j;
                const int pp = 8 * (k1 & 3) + 2 * ((k1 >> 2) & 3) + (k1 >> 4);
                float twc, tws;
                if (j == 0)      { twc = wc; tws = ws; }
                else if (j == 1) { twc = wc * bc - ws * bs;   tws = wc * bs + ws * bc; }
                else if (j == 2) { twc = wc * b2c - ws * b2s; tws = wc * b2s + ws * b2c; }
                else             { twc = wc * b3c - ws * b3s; tws = wc * b3s + ws * b3c; }
                TR[32 * k1 + (lane ^ k1)] =
                    make_float2(zr[pp] * twc - zi[pp] * tws,
                                zr[pp] * tws + zi[pp] * twc);
            }
            float nc = wc * b4c - ws * b4s, ns = wc * b4s + ws * b4c;
            wc = nc; ws = ns;
        }
    }
    __syncwarp();

    // ---- step 2: pruned streaming 32-pt DFT over n2 (thread = row k1 = lane).
    //      Needed k2 in {0,1,2,3,28,29,30,31}: Y[k2] = sum_j W32^{j*k2} V_j[k2&3],
    //      V_j[r] = 4-pt DFT over m of row[j+8m]. All twiddles literal. ----
    float accR[8] = {0,0,0,0,0,0,0,0}, accI[8] = {0,0,0,0,0,0,0,0};
    {
        constexpr float C32[32] = {
            1.0f, 0.98078528040323044913f, 0.92387953251128675613f, 0.83146961230254523708f,
            0.70710678118654752440f, 0.55557023301960222474f, 0.38268343236508977173f,
            0.19509032201612826785f, 0.0f, -0.19509032201612826785f, -0.38268343236508977173f,
            -0.55557023301960222474f, -0.70710678118654752440f, -0.83146961230254523708f,
            -0.92387953251128675613f, -0.98078528040323044913f, -1.0f,
            -0.98078528040323044913f, -0.92387953251128675613f, -0.83146961230254523708f,
            -0.70710678118654752440f, -0.55557023301960222474f, -0.38268343236508977173f,
            -0.19509032201612826785f, 0.0f, 0.19509032201612826785f, 0.38268343236508977173f,
            0.55557023301960222474f, 0.70710678118654752440f, 0.83146961230254523708f,
            0.92387953251128675613f, 0.98078528040323044913f };
        constexpr float S32[32] = {
            0.0f, -0.19509032201612826785f, -0.38268343236508977173f, -0.55557023301960222474f,
            -0.70710678118654752440f, -0.83146961230254523708f, -0.92387953251128675613f,
            -0.98078528040323044913f, -1.0f, -0.98078528040323044913f,
            -0.92387953251128675613f, -0.83146961230254523708f, -0.70710678118654752440f,
            -0.55557023301960222474f, -0.38268343236508977173f, -0.19509032201612826785f,
            0.0f, 0.19509032201612826785f, 0.38268343236508977173f, 0.55557023301960222474f,
            0.70710678118654752440f, 0.83146961230254523708f, 0.92387953251128675613f,
            0.98078528040323044913f, 1.0f, 0.98078528040323044913f, 0.92387953251128675613f,
            0.83146961230254523708f, 0.70710678118654752440f, 0.55557023301960222474f,
            0.38268343236508977173f, 0.19509032201612826785f };
        constexpr int K2V[8] = {0, 1, 2, 3, 28, 29, 30, 31};

        #pragma unroll
        for (int j = 0; j < 8; ++j) {
            float2 a0 = TR[32 * lane + ((j     ) ^ lane)];
            float2 a1 = TR[32 * lane + ((j +  8) ^ lane)];
            float2 a2 = TR[32 * lane + ((j + 16) ^ lane)];
            float2 a3 = TR[32 * lane + ((j + 24) ^ lane)];
            float t0r = a0.x + a2.x, t0i = a0.y + a2.y;
            float t1r = a1.x + a3.x, t1i = a1.y + a3.y;
            float t2r = a0.x - a2.x, t2i = a0.y - a2.y;
            float t3r = a1.x - a3.x, t3i = a1.y - a3.y;
            float VR[4], VI[4];
            VR[0] = t0r + t1r;  VI[0] = t0i + t1i;
            VR[2] = t0r - t1r;  VI[2] = t0i - t1i;
            VR[1] = t2r + t3i;  VI[1] = t2i - t3r;     // t2 - i*t3
            VR[3] = t2r - t3i;  VI[3] = t2i + t3r;     // t2 + i*t3
            #pragma unroll
            for (int q = 0; q < 8; ++q) {
                const int k2 = K2V[q];
                const int r  = k2 & 3;
                const int tt = (k2 * j) & 31;
                accR[q] = fmaf(C32[tt], VR[r], fmaf(-S32[tt], VI[r], accR[q]));
                accI[q] = fmaf(C32[tt], VI[r], fmaf( S32[tt], VR[r], accI[q]));
            }
        }
    }
    __syncwarp();   // all TR reads done before SPX (aliased) writes

    // ---- rfft unpack in registers via shuffles -> SPX[0..102] ----
    // Thread lane holds bins lane+32q (q=0..3) and lane+896+32(q-4) (q=4..7).
    // Partner of bin k=lane+32q is bin 1024-k = (32-lane)&31 thread, acc[7-q]
    // (lane 0, q>=1: its own acc[8-q]; lane 0, q==0: conj self).
    {
        const int src = (32 - lane) & 31;
        #pragma unroll
        for (int q = 0; q < 4; ++q) {
            float br = __shfl_sync(FM, accR[7 - q], src);
            float bi = __shfl_sync(FM, accI[7 - q], src);
            if (lane == 0 && q > 0) { br = accR[8 - q]; bi = accI[8 - q]; }
            float Ar = accR[q], Ai = accI[q];
            float Br, Bi;
            if (q == 0 && lane == 0) { Br = Ar; Bi = Ai; }
            else                     { Br = br; Bi = bi; }
            int k = lane + 32 * q;
            float zer =  0.5f * (Ar + Br);
            float zei =  0.5f * (Ai - Bi);
            float zor =  0.5f * (Ai + Bi);
            float zoi = -0.5f * (Ar - Br);
            float sn, cs;
            __sincosf((float)k * (-3.141592653589793f / 1024.0f), &sn, &cs);
            if (q < 3 || lane <= 6)
                SPX[k] = make_float2(zer + cs * zor - sn * zoi,
                                     zei + cs * zoi + sn * zor);
        }
    }
    __syncwarp();

    // ---- window as spectral conv + log magnitude -> LA[0..101] ----
    #pragma unroll
    for (int it = 0; it < 4; ++it) {
        int k = lane + 32 * it;
        if (it < 3 || lane <= 5) {      // k < 102
            float2 Xc = SPX[k];
            float2 Xp = SPX[k + 1];
            float2 Xm = (k == 0) ? make_float2(SPX[1].x, -SPX[1].y) : SPX[k - 1];
            float xr = 0.5f * Xc.x - 0.25f * (Xm.x + Xp.x);
            float xi = 0.5f * Xc.y - 0.25f * (Xm.y + Xp.y);
            LA[k] = __logf(sqrtf(xr * xr + xi * xi) + 1e-8f);
        }
    }
    if (lane < 2) LA[KLA + lane] = 0.f;
    #pragma unroll
    for (int i = lane; i < LPAD / 4; i += 32)
        reinterpret_cast<float4*>(LSB)[i] = make_float4(0.f, 0.f, 0.f, 0.f);
    __syncwarp();

    // ---- single-pass warp scan: CS1 inclusive prefix of LA ----
    {
        float v0 = 0.f, v1 = 0.f, v2 = 0.f, v3 = 0.f;
        if (lane < 26) {
            float4 q = reinterpret_cast<const float4*>(LA)[lane];
            v0 = q.x; v1 = q.y; v2 = q.z; v3 = q.w;
        }
        float p1 = v0 + v1, p2 = p1 + v2, p3 = p2 + v3;
        float s = p3;
        #pragma unroll
        for (int o = 1; o < 32; o <<= 1) {
            float u = __shfl_up_sync(FM, s, o);
            if (lane >= o) s += u;
        }
        float excl = s - p3;
        if (lane < 26)
            reinterpret_cast<float4*>(CS1)[lane] =
                make_float4(excl + v0, excl + p1, excl + p2, excl + p3);
    }
    __syncwarp();

    // ---- fine structure: 8 pitch bins per thread (two float4 groups) ----
    float lsv[2][4];
    #pragma unroll
    for (int g = 0; g < 2; ++g) {
        int vt = lane + 32 * g;
        int4 c4 = reinterpret_cast<const int4*>(p.closest)[vt];
        int cis[4] = {c4.x, c4.y, c4.z, c4.w};
        float LA0 = LA[0];
        #pragma unroll
        for (int j = 0; j < 4; ++j) {
            int ci = cis[j];                  // 3..85
            int lo = ci - 15, hi = ci + 16;   // hi <= 101
            float sum = (lo <= 0) ? fmaf((float)(-lo), LA0, CS1[hi])
                                  : CS1[hi] - CS1[lo - 1];
            lsv[g][j] = __expf(LA[ci] - sum * 0.03125f);
        }
        *reinterpret_cast<float4*>(&LSB[LPAD + 4 * vt]) =
            make_float4(lsv[g][0], lsv[g][1], lsv[g][2], lsv[g][3]);
    }
    __syncwarp();

    // ---- subharmonic summation (zero-padded, guard-free) ----
    float acc[2][4];
    #pragma unroll
    for (int g = 0; g < 2; ++g)
        #pragma unroll
        for (int j = 0; j < 4; ++j) acc[g][j] = lsv[g][j];

    #pragma unroll
    for (int n = 1; n < 8; ++n) {
        int   sh = p.shift[n];
        float wn = p.wgt[n];
        #pragma unroll
        for (int g = 0; g < 2; ++g) {
            int bi = LPAD + 4 * (lane + 32 * g) - sh;     // >= 3 always
            if ((sh & 3) == 0) {
                float4 q = *reinterpret_cast<const float4*>(&LSB[bi]);
                acc[g][0] = fmaf(wn, q.x, acc[g][0]);
                acc[g][1] = fmaf(wn, q.y, acc[g][1]);
                acc[g][2] = fmaf(wn, q.z, acc[g][2]);
                acc[g][3] = fmaf(wn, q.w, acc[g][3]);
            } else if ((sh & 1) == 0) {
                float2 qa = *reinterpret_cast<const float2*>(&LSB[bi]);
                float2 qb = *reinterpret_cast<const float2*>(&LSB[bi + 2]);
                acc[g][0] = fmaf(wn, qa.x, acc[g][0]);
                acc[g][1] = fmaf(wn, qa.y, acc[g][1]);
                acc[g][2] = fmaf(wn, qb.x, acc[g][2]);
                acc[g][3] = fmaf(wn, qb.y, acc[g][3]);
            } else {
                #pragma unroll
                for (int j = 0; j < 4; ++j)
                    acc[g][j] = fmaf(wn, LSB[bi + j], acc[g][j]);
            }
        }
    }

    // ---- per-frame max (pure warp shuffle), normalize, store ----
    float mloc = -3.4e38f;
    #pragma unroll
    for (int g = 0; g < 2; ++g)
        #pragma unroll
        for (int j = 0; j < 4; ++j) mloc = fmaxf(mloc, acc[g][j]);
    #pragma unroll
    for (int o = 16; o; o >>= 1)
        mloc = fmaxf(mloc, __shfl_xor_sync(FM, mloc, o));
    float mx = fmaxf(mloc, 1e-8f);

    float4* optr = reinterpret_cast<float4*>(out + ((size_t)b * TFRAMES + t) * NPITCH);
    #pragma unroll
    for (int g = 0; g < 2; ++g) {
        float4 o4;
        o4.x = __fdividef(acc[g][0], mx);
        o4.y = __fdividef(acc[g][1], mx);
        o4.z = __fdividef(acc[g][2], mx);
        o4.w = __fdividef(acc[g][3], mx);
        optr[lane + 32 * g] = o4;
    }
}

extern "C" void kernel_launch(void* const* d_in, const int* in_sizes, int n_in,
                              void* d_out, int out_size)
{
    (void)in_sizes; (void)n_in; (void)out_size;
    const float* wav = (const float*)d_in[0];
    float* out = (float*)d_out;

    Params p;

    // Gather indices: f32 argmin over |linspace(0,12000,1025) - center_freq|
    const double l40 = log(40.0), l1000 = log(1000.0);
    for (int j = 0; j < NPITCH; ++j) {
        double cd = exp(l40 + (double)j * (l1000 - l40) / 255.0);
        float  cf = (float)cd;
        const float step = 11.71875f;
        int i0 = (int)(cd / 11.71875);
        int best = 0; float bestd = 3.4e38f;
        for (int i = i0 - 2; i <= i0 + 2; ++i) {
            int ic = i < 0 ? 0 : (i > 1024 ? 1024 : i);
            float d = fabsf((float)ic * step - cf);
            if (d < bestd) { bestd = d; best = ic; }
        }
        p.closest[j] = best;
    }

    // Harmonic shifts: Python round() == rint (half-even), identical expression
    const double cpb = 1200.0 * log2(25.0) / 255.0;
    p.shift[0] = 0; p.wgt[0] = 1.0f;
    for (int n = 2; n <= 8; ++n) {
        p.shift[n - 1] = (int)rint(1200.0 * log2((double)n) / cpb);
        p.wgt[n - 1]   = (float)pow(0.86, (double)(n - 1));
    }

    dim3 grid(TFRAMES, BATCH);
    pitch_kernel<<<grid, 32>>>(wav, out, p);
}

// round 14
// speedup vs baseline: 1.1253x; 1.0395x over previous
#include <cuda_runtime.h>
#include <math.h>
#include <stdint.h>

// Fixed problem shapes
#define HOP 256
#define NFFT 2048
#define NPITCH 256
#define BATCH 16
#define NSAMP 480000
#define TFRAMES 1876
#define KLA 102           // LA bins 0..101
#define LPAD 168          // zero-pad in front of LS (max shift 165)

struct Params {
    int   closest[NPITCH];
    int   shift[8];
    float wgt[8];
};

#define CR 0.7071067811865476f

__device__ __forceinline__ void bfly4(
    float& r0, float& i0, float& r1, float& i1,
    float& r2, float& i2, float& r3, float& i3,
    float c1, float s1, float c2, float s2, float c3, float s3)
{
    float t0r = r0 + r2, t0i = i0 + i2;
    float t1r = r1 + r3, t1i = i1 + i3;
    float t2r = r0 - r2, t2i = i0 - i2;
    float t3r = r1 - r3, t3i = i1 - i3;
    float y0r = t0r + t1r, y0i = t0i + t1i;
    float y2r = t0r - t1r, y2i = t0i - t1i;
    float y1r = t2r + t3i, y1i = t2i - t3r;
    float y3r = t2r - t3i, y3i = t2i + t3r;
    r0 = y0r;                 i0 = y0i;
    r1 = y1r * c1 - y1i * s1; i1 = y1r * s1 + y1i * c1;
    r2 = y2r * c2 - y2i * s2; i2 = y2r * s2 + y2i * c2;
    r3 = y3r * c3 - y3i * s3; i3 = y3r * s3 + y3i * c3;
}

// In-register 32-pt DIF FFT (radix 4,4,2). Output position p holds bin
// k = (p>>3) + 4*((p>>1)&3) + 16*(p&1). All twiddles are literals.
__device__ __forceinline__ void fft32(float* zr, float* zi)
{
    constexpr float T32C[8] = { 1.0f, 0.98078528040323044913f, 0.92387953251128675613f,
        0.83146961230254523708f, 0.70710678118654752440f, 0.55557023301960222474f,
        0.38268343236508977173f, 0.19509032201612826785f };
    constexpr float T32S[8] = { 0.0f, -0.19509032201612826785f, -0.38268343236508977173f,
        -0.55557023301960222474f, -0.70710678118654752440f, -0.83146961230254523708f,
        -0.92387953251128675613f, -0.98078528040323044913f };
    constexpr float T16C[8] = { 1.0f, 0.92387953251128675613f, 0.70710678118654752440f,
        0.38268343236508977173f, 0.0f, -0.38268343236508977173f,
        -0.70710678118654752440f, -0.92387953251128675613f };
    constexpr float T16S[8] = { 0.0f, -0.38268343236508977173f, -0.70710678118654752440f,
        -0.92387953251128675613f, -1.0f, -0.92387953251128675613f,
        -0.70710678118654752440f, -0.38268343236508977173f };
    constexpr float T96C[8] = { 1.0f, 0.83146961230254523708f, 0.38268343236508977173f,
        -0.19509032201612826785f, -0.70710678118654752440f, -0.98078528040323044913f,
        -0.92387953251128675613f, -0.55557023301960222474f };
    constexpr float T96S[8] = { 0.0f, -0.55557023301960222474f, -0.92387953251128675613f,
        -0.98078528040323044913f, -0.70710678118654752440f, -0.19509032201612826785f,
        0.38268343236508977173f, 0.83146961230254523708f };

    #pragma unroll
    for (int q = 0; q < 8; ++q)
        bfly4(zr[q], zi[q], zr[q + 8], zi[q + 8], zr[q + 16], zi[q + 16],
              zr[q + 24], zi[q + 24],
              T32C[q], T32S[q], T16C[q], T16S[q], T96C[q], T96S[q]);

    #pragma unroll
    for (int g = 0; g < 4; ++g) {
        const int bb = 8 * g;
        bfly4(zr[bb], zi[bb], zr[bb + 2], zi[bb + 2], zr[bb + 4], zi[bb + 4],
              zr[bb + 6], zi[bb + 6], 1.f, 0.f, 1.f, 0.f, 1.f, 0.f);
        bfly4(zr[bb + 1], zi[bb + 1], zr[bb + 3], zi[bb + 3], zr[bb + 5], zi[bb + 5],
              zr[bb + 7], zi[bb + 7], CR, -CR, 0.f, -1.f, -CR, -CR);
    }

    #pragma unroll
    for (int m = 0; m < 16; ++m) {
        float ar = zr[2 * m], ai = zi[2 * m];
        float br = zr[2 * m + 1], bi = zi[2 * m + 1];
        zr[2 * m] = ar + br;     zi[2 * m] = ai + bi;
        zr[2 * m + 1] = ar - br; zi[2 * m + 1] = ai - bi;
    }
}

__global__ __launch_bounds__(32, 24)
void pitch_kernel(const float* __restrict__ wav, float* __restrict__ out, Params p)
{
    // TR: XOR-swizzled 32x32 float2 transpose buffer (exactly 1024 f2 = 8192 B).
    // After TR is consumed, SPX/LA/CS1/LSB alias the same storage.
    __shared__ __align__(16) float SH[2048];
    float2* TR  = reinterpret_cast<float2*>(SH);
    float2* SPX = reinterpret_cast<float2*>(SH);            // bins 0..102 (f2[0..103))
    float*  LA  = SH + 208;                                 // [208,312)
    float*  CS1 = SH + 312;                                 // [312,416)
    float*  LSB = SH + 416;                                 // [416,840)

    const int lane = threadIdx.x;     // 0..31
    const int t    = blockIdx.x;
    const int b    = blockIdx.y;
    const float* w = wav + (size_t)b * NSAMP;
    const int base = t * HOP - (NFFT / 2);
    const unsigned FM = 0xffffffffu;

    // ---- load: thread n2=lane holds packed z[32*n1 + lane], n1 = 0..31 ----
    float zr[32], zi[32];
    if (base >= 0 && base + NFFT <= NSAMP) {
        const float2* src = reinterpret_cast<const float2*>(w + base);
        #pragma unroll
        for (int n1 = 0; n1 < 32; ++n1) {
            float2 v = src[32 * n1 + lane];
            zr[n1] = v.x; zi[n1] = v.y;
        }
    } else {
        #pragma unroll
        for (int n1 = 0; n1 < 32; ++n1) {
            int m  = 32 * n1 + lane;
            int p0 = base + 2 * m, p1 = p0 + 1;
            p0 = p0 < 0 ? -p0 : (p0 >= NSAMP ? 2 * NSAMP - 2 - p0 : p0);
            p1 = p1 < 0 ? -p1 : (p1 >= NSAMP ? 2 * NSAMP - 2 - p1 : p1);
            zr[n1] = w[p0]; zi[n1] = w[p1];
        }
    }

    // ---- step 1: full 32-pt FFT over n1 ----
    fft32(zr, zi);

    // ---- twiddle W1024^{n2*k1} and transpose-store (row k1, XOR swizzle) ----
    {
        float bs, bc; __sincosf((float)lane * (-6.283185307179586f / 1024.0f), &bs, &bc);
        float b2c = bc * bc - bs * bs, b2s = 2.0f * bc * bs;
        float b3c = bc * b2c - bs * b2s, b3s = bc * b2s + bs * b2c;
        float b4c = b2c * b2c - b2s * b2s, b4s = 2.0f * b2c * b2s;
        float wc = 1.0f, ws = 0.0f;            // W^(4*j32*lane)
        #pragma unroll
        for (int j32 = 0; j32 < 8; ++j32) {
            #pragma unroll
            for (int j = 0; j < 4; ++j) {
                const int k1 = 4 * j32 + j;
                const int pp = 8 * (k1 & 3) + 2 * ((k1 >> 2) & 3) + (k1 >> 4);
                float twc, tws;
                if (j == 0)      { twc = wc; tws = ws; }
                else if (j == 1) { twc = wc * bc - ws * bs;   tws = wc * bs + ws * bc; }
                else if (j == 2) { twc = wc * b2c - ws * b2s; tws = wc * b2s + ws * b2c; }
                else             { twc = wc * b3c - ws * b3s; tws = wc * b3s + ws * b3c; }
                TR[32 * k1 + (lane ^ k1)] =
                    make_float2(zr[pp] * twc - zi[pp] * tws,
                                zr[pp] * tws + zi[pp] * twc);
            }
            float nc = wc * b4c - ws * b4s, ns = wc * b4s + ws * b4c;
            wc = nc; ws = ns;
        }
    }
    __syncwarp();

    // ---- step 2: pruned streaming 32-pt DFT over n2 (thread = row k1 = lane).
    //      Needed k2 in {0,1,2,3,28,29,30,31}: Y[k2] = sum_j W32^{j*k2} V_j[k2&3],
    //      V_j[r] = 4-pt DFT over m of row[j+8m]. All twiddles literal. ----
    float accR[8] = {0,0,0,0,0,0,0,0}, accI[8] = {0,0,0,0,0,0,0,0};
    {
        constexpr float C32[32] = {
            1.0f, 0.98078528040323044913f, 0.92387953251128675613f, 0.83146961230254523708f,
            0.70710678118654752440f, 0.55557023301960222474f, 0.38268343236508977173f,
            0.19509032201612826785f, 0.0f, -0.19509032201612826785f, -0.38268343236508977173f,
            -0.55557023301960222474f, -0.70710678118654752440f, -0.83146961230254523708f,
            -0.92387953251128675613f, -0.98078528040323044913f, -1.0f,
            -0.98078528040323044913f, -0.92387953251128675613f, -0.83146961230254523708f,
            -0.70710678118654752440f, -0.55557023301960222474f, -0.38268343236508977173f,
            -0.19509032201612826785f, 0.0f, 0.19509032201612826785f, 0.38268343236508977173f,
            0.55557023301960222474f, 0.70710678118654752440f, 0.83146961230254523708f,
            0.92387953251128675613f, 0.98078528040323044913f };
        constexpr float S32[32] = {
            0.0f, -0.19509032201612826785f, -0.38268343236508977173f, -0.55557023301960222474f,
            -0.70710678118654752440f, -0.83146961230254523708f, -0.92387953251128675613f,
            -0.98078528040323044913f, -1.0f, -0.98078528040323044913f,
            -0.92387953251128675613f, -0.83146961230254523708f, -0.70710678118654752440f,
            -0.55557023301960222474f, -0.38268343236508977173f, -0.19509032201612826785f,
            0.0f, 0.19509032201612826785f, 0.38268343236508977173f, 0.55557023301960222474f,
            0.70710678118654752440f, 0.83146961230254523708f, 0.92387953251128675613f,
            0.98078528040323044913f, 1.0f, 0.98078528040323044913f, 0.92387953251128675613f,
            0.83146961230254523708f, 0.70710678118654752440f, 0.55557023301960222474f,
            0.38268343236508977173f, 0.19509032201612826785f };
        constexpr int K2V[8] = {0, 1, 2, 3, 28, 29, 30, 31};

        #pragma unroll
        for (int j = 0; j < 8; ++j) {
            float2 a0 = TR[32 * lane + ((j     ) ^ lane)];
            float2 a1 = TR[32 * lane + ((j +  8) ^ lane)];
            float2 a2 = TR[32 * lane + ((j + 16) ^ lane)];
            float2 a3 = TR[32 * lane + ((j + 24) ^ lane)];
            float t0r = a0.x + a2.x, t0i = a0.y + a2.y;
            float t1r = a1.x + a3.x, t1i = a1.y + a3.y;
            float t2r = a0.x - a2.x, t2i = a0.y - a2.y;
            float t3r = a1.x - a3.x, t3i = a1.y - a3.y;
            float VR[4], VI[4];
            VR[0] = t0r + t1r;  VI[0] = t0i + t1i;
            VR[2] = t0r - t1r;  VI[2] = t0i - t1i;
            VR[1] = t2r + t3i;  VI[1] = t2i - t3r;     // t2 - i*t3
            VR[3] = t2r - t3i;  VI[3] = t2i + t3r;     // t2 + i*t3
            #pragma unroll
            for (int q = 0; q < 8; ++q) {
                const int k2 = K2V[q];
                const int r  = k2 & 3;
                const int tt = (k2 * j) & 31;
                accR[q] = fmaf(C32[tt], VR[r], fmaf(-S32[tt], VI[r], accR[q]));
                accI[q] = fmaf(C32[tt], VI[r], fmaf( S32[tt], VR[r], accI[q]));
            }
        }
    }
    __syncwarp();   // all TR reads done before SPX (aliased) writes

    // ---- rfft unpack in registers via shuffles -> SPX[0..102] ----
    // Thread lane holds bins lane+32q (q=0..3) and lane+896+32(q-4) (q=4..7).
    // Partner of bin k=lane+32q is bin 1024-k = (32-lane)&31 thread, acc[7-q]
    // (lane 0, q>=1: its own acc[8-q]; lane 0, q==0: conj self).
    {
        const int src = (32 - lane) & 31;
        #pragma unroll
        for (int q = 0; q < 4; ++q) {
            float br = __shfl_sync(FM, accR[7 - q], src);
            float bi = __shfl_sync(FM, accI[7 - q], src);
            if (lane == 0 && q > 0) { br = accR[8 - q]; bi = accI[8 - q]; }
            float Ar = accR[q], Ai = accI[q];
            float Br, Bi;
            if (q == 0 && lane == 0) { Br = Ar; Bi = Ai; }
            else                     { Br = br; Bi = bi; }
            int k = lane + 32 * q;
            float zer =  0.5f * (Ar + Br);
            float zei =  0.5f * (Ai - Bi);
            float zor =  0.5f * (Ai + Bi);
            float zoi = -0.5f * (Ar - Br);
            float sn, cs;
            __sincosf((float)k * (-3.141592653589793f / 1024.0f), &sn, &cs);
            if (q < 3 || lane <= 6)
                SPX[k] = make_float2(zer + cs * zor - sn * zoi,
                                     zei + cs * zoi + sn * zor);
        }
    }
    __syncwarp();

    // ---- window as spectral conv + log magnitude -> LA[0..101] ----
    #pragma unroll
    for (int it = 0; it < 4; ++it) {
        int k = lane + 32 * it;
        if (it < 3 || lane <= 5) {      // k < 102
            float2 Xc = SPX[k];
            float2 Xp = SPX[k + 1];
            float2 Xm = (k == 0) ? make_float2(SPX[1].x, -SPX[1].y) : SPX[k - 1];
            float xr = 0.5f * Xc.x - 0.25f * (Xm.x + Xp.x);
            float xi = 0.5f * Xc.y - 0.25f * (Xm.y + Xp.y);
            LA[k] = __logf(sqrtf(xr * xr + xi * xi) + 1e-8f);
        }
    }
    if (lane < 2) LA[KLA + lane] = 0.f;
    #pragma unroll
    for (int i = lane; i < LPAD / 4; i += 32)
        reinterpret_cast<float4*>(LSB)[i] = make_float4(0.f, 0.f, 0.f, 0.f);
    __syncwarp();

    // ---- single-pass warp scan: CS1 inclusive prefix of LA ----
    {
        float v0 = 0.f, v1 = 0.f, v2 = 0.f, v3 = 0.f;
        if (lane < 26) {
            float4 q = reinterpret_cast<const float4*>(LA)[lane];
            v0 = q.x; v1 = q.y; v2 = q.z; v3 = q.w;
        }
        float p1 = v0 + v1, p2 = p1 + v2, p3 = p2 + v3;
        float s = p3;
        #pragma unroll
        for (int o = 1; o < 32; o <<= 1) {
            float u = __shfl_up_sync(FM, s, o);
            if (lane >= o) s += u;
        }
        float excl = s - p3;
        if (lane < 26)
            reinterpret_cast<float4*>(CS1)[lane] =
                make_float4(excl + v0, excl + p1, excl + p2, excl + p3);
    }
    __syncwarp();

    // ---- fine structure: 8 pitch bins per thread (two float4 groups) ----
    float lsv[2][4];
    #pragma unroll
    for (int g = 0; g < 2; ++g) {
        int vt = lane + 32 * g;
        int4 c4 = reinterpret_cast<const int4*>(p.closest)[vt];
        int cis[4] = {c4.x, c4.y, c4.z, c4.w};
        float LA0 = LA[0];
        #pragma unroll
        for (int j = 0; j < 4; ++j) {
            int ci = cis[j];                  // 3..85
            int lo = ci - 15, hi = ci + 16;   // hi <= 101
            float sum = (lo <= 0) ? fmaf((float)(-lo), LA0, CS1[hi])
                                  : CS1[hi] - CS1[lo - 1];
            lsv[g][j] = __expf(LA[ci] - sum * 0.03125f);
        }
        *reinterpret_cast<float4*>(&LSB[LPAD + 4 * vt]) =
            make_float4(lsv[g][0], lsv[g][1], lsv[g][2], lsv[g][3]);
    }
    __syncwarp();

    // ---- subharmonic summation (zero-padded, guard-free) ----
    float acc[2][4];
    #pragma unroll
    for (int g = 0; g < 2; ++g)
        #pragma unroll
        for (int j = 0; j < 4; ++j) acc[g][j] = lsv[g][j];

    #pragma unroll
    for (int n = 1; n < 8; ++n) {
        int   sh = p.shift[n];
        float wn = p.wgt[n];
        #pragma unroll
        for (int g = 0; g < 2; ++g) {
            int bi = LPAD + 4 * (lane + 32 * g) - sh;     // >= 3 always
            if ((sh & 3) == 0) {
                float4 q = *reinterpret_cast<const float4*>(&LSB[bi]);
                acc[g][0] = fmaf(wn, q.x, acc[g][0]);
                acc[g][1] = fmaf(wn, q.y, acc[g][1]);
                acc[g][2] = fmaf(wn, q.z, acc[g][2]);
                acc[g][3] = fmaf(wn, q.w, acc[g][3]);
            } else if ((sh & 1) == 0) {
                float2 qa = *reinterpret_cast<const float2*>(&LSB[bi]);
                float2 qb = *reinterpret_cast<const float2*>(&LSB[bi + 2]);
                acc[g][0] = fmaf(wn, qa.x, acc[g][0]);
                acc[g][1] = fmaf(wn, qa.y, acc[g][1]);
                acc[g][2] = fmaf(wn, qb.x, acc[g][2]);
                acc[g][3] = fmaf(wn, qb.y, acc[g][3]);
            } else {
                #pragma unroll
                for (int j = 0; j < 4; ++j)
                    acc[g][j] = fmaf(wn, LSB[bi + j], acc[g][j]);
            }
        }
    }

    // ---- per-frame max (pure warp shuffle), normalize, store ----
    float mloc = -3.4e38f;
    #pragma unroll
    for (int g = 0; g < 2; ++g)
        #pragma unroll
        for (int j = 0; j < 4; ++j) mloc = fmaxf(mloc, acc[g][j]);
    #pragma unroll
    for (int o = 16; o; o >>= 1)
        mloc = fmaxf(mloc, __shfl_xor_sync(FM, mloc, o));
    float mx = fmaxf(mloc, 1e-8f);

    float4* optr = reinterpret_cast<float4*>(out + ((size_t)b * TFRAMES + t) * NPITCH);
    #pragma unroll
    for (int g = 0; g < 2; ++g) {
        float4 o4;
        o4.x = __fdividef(acc[g][0], mx);
        o4.y = __fdividef(acc[g][1], mx);
        o4.z = __fdividef(acc[g][2], mx);
        o4.w = __fdividef(acc[g][3], mx);
        optr[lane + 32 * g] = o4;
    }
}

extern "C" void kernel_launch(void* const* d_in, const int* in_sizes, int n_in,
                              void* d_out, int out_size)
{
    (void)in_sizes; (void)n_in; (void)out_size;
    const float* wav = (const float*)d_in[0];
    float* out = (float*)d_out;

    Params p;

    // Gather indices: f32 argmin over |linspace(0,12000,1025) - center_freq|
    const double l40 = log(40.0), l1000 = log(1000.0);
    for (int j = 0; j < NPITCH; ++j) {
        double cd = exp(l40 + (double)j * (l1000 - l40) / 255.0);
        float  cf = (float)cd;
        const float step = 11.71875f;
        int i0 = (int)(cd / 11.71875);
        int best = 0; float bestd = 3.4e38f;
        for (int i = i0 - 2; i <= i0 + 2; ++i) {
            int ic = i < 0 ? 0 : (i > 1024 ? 1024 : i);
            float d = fabsf((float)ic * step - cf);
            if (d < bestd) { bestd = d; best = ic; }
        }
        p.closest[j] = best;
    }

    // Harmonic shifts: Python round() == rint (half-even), identical expression
    const double cpb = 1200.0 * log2(25.0) / 255.0;
    p.shift[0] = 0; p.wgt[0] = 1.0f;
    for (int n = 2; n <= 8; ++n) {
        p.shift[n - 1] = (int)rint(1200.0 * log2((double)n) / cpb);
        p.wgt[n - 1]   = (float)pow(0.86, (double)(n - 1));
    }

    dim3 grid(TFRAMES, BATCH);
    pitch_kernel<<<grid, 32>>>(wav, out, p);
}